// round 12
// baseline (speedup 1.0000x reference)
#include <cuda_runtime.h>
#include <cuda_bf16.h>

// FocalLoss: inputs [B, A] f32 probs, targets [A, B] i32 {0,1}, attr_loss_weight [A] f32.
// loss = sum_b mean_a( aw[a] * (1-x)^2 * bce(x, t) ),  bce = -log(t ? clamp(x) : 1-clamp(x))
// B = 1e6, A = 40.  ~324 MB streaming reduction.
//
// R9: cp.async target staging (no registers), NB=64 / 640 threads => exactly 1 item
// per thread (no predicates/arrays), 3-buffer rotation with 1 sync/chunk,
// XOR-mod7 smem swizzle to kill the 5-way LDS bank conflict, 94% occupancy.

#define A_NUM    40
#define NB       64                 // samples per chunk; 1e6 / 64 = 15625 chunks
#define NT       640                // threads; NB*A/4 = 640 items = 1 per thread
#define GRID     444                // 148 SMs * 3 CTAs
#define ROWB     272                // bytes per attr row in smem (68 ints, 16B aligned)
#define BUFB     (A_NUM * ROWB)     // 10880 B per buffer
#define NBUF     3

#define LN2_F 0.6931471805599453f

__global__ void fl_init_out(float* out) {
    if (threadIdx.x == 0) out[0] = 0.0f;
}

__device__ __forceinline__ void cpa16(unsigned s, const void* g) {
    asm volatile("cp.async.cg.shared.global [%0], [%1], 16;\n" :: "r"(s), "l"(g));
}
#define CPA_COMMIT() asm volatile("cp.async.commit_group;\n" ::: "memory")
#define CPA_WAIT0()  asm volatile("cp.async.wait_group 0;\n" ::: "memory")

__device__ __forceinline__ float fl_elem(float x, int t, float w) {
    // p = max(x,1e-12); upper clip (1-1e-12) rounds to 1.0f in f32 -> no-op.
    // (1-x)^2 == (1-p)^2 exactly (for x < 1e-12 both round to 1.0f).
    float p   = fmaxf(x, 1e-12f);
    float omp = 1.0f - p;
    float q   = t ? p : omp;
    return -w * (omp * omp) * __log2f(q);   // w includes aw*ln2/A
}

__global__ __launch_bounds__(NT, 3) void focal_loss_kernel(
    const float* __restrict__ in,     // [B, A]
    const int*   __restrict__ tg,     // [A, B]
    const float* __restrict__ aw,     // [A]
    float*       __restrict__ out,    // scalar
    int B, int A)
{
    float acc = 0.0f;
    const int tid = threadIdx.x;

    if (A == A_NUM && (B % NB) == 0 && blockDim.x == NT) {
        __shared__ __align__(16) float awv[A_NUM];
        __shared__ __align__(16) char  ts[NBUF * BUFB];   // 32640 B target stage

        if (tid < A_NUM) awv[tid] = aw[tid] * (LN2_F / (float)A_NUM);

        const float4* __restrict__ in4 = reinterpret_cast<const float4*>(in);
        const int nchunks = B / NB;                // 15625

        // ---- compute-side constants (1 item per thread) ----
        const int b  = tid / 10;                   // sample within chunk, 0..63
        const int a4 = 4 * (tid - 10 * b);         // first attr, {0,4,...,36}
        // swizzled read byte-offsets for targets (a4+j, b), j=0..3
        int roff[4];
        #pragma unroll
        for (int j = 0; j < 4; j++) {
            int a = a4 + j;
            roff[j] = a * ROWB + 16 * ((b >> 2) ^ (a % 7)) + 4 * (b & 3);
        }

        // ---- prefetch-side constants ----
        const int ta = tid >> 4;                   // attr row, 0..39
        const int tr = tid & 15;                   // 16B chunk within row, 0..15
        const int* gsrc = tg + (size_t)ta * B + 4 * tr;
        const unsigned sbase = (unsigned)__cvta_generic_to_shared(ts);
        const unsigned woff  = ta * ROWB + 16 * (tr ^ (ta % 7));

        const int c0 = blockIdx.x;

        // ---- prologue: stage chunk c0 into buffer 0 ----
        cpa16(sbase + woff, gsrc + c0 * NB);
        CPA_COMMIT();
        CPA_WAIT0();
        __syncthreads();

        const float4 w4 = *reinterpret_cast<const float4*>(awv + a4);

        int cur = 0;
        for (int c = c0; c < nchunks; c += GRID) {
            const int cnx = c + GRID;
            const int nxt = (cur == NBUF - 1) ? 0 : cur + 1;

            // stage next chunk (flies during compute)
            if (cnx < nchunks)
                cpa16(sbase + nxt * BUFB + woff, gsrc + cnx * NB);
            CPA_COMMIT();

            // stream input (perfectly coalesced, evict-first)
            float4 x = __ldcs(&in4[c * NT + tid]);

            // targets from staged smem (<=2-way conflicts via swizzle)
            const char* tb = ts + cur * BUFB;
            int t0 = *reinterpret_cast<const int*>(tb + roff[0]);
            int t1 = *reinterpret_cast<const int*>(tb + roff[1]);
            int t2 = *reinterpret_cast<const int*>(tb + roff[2]);
            int t3 = *reinterpret_cast<const int*>(tb + roff[3]);

            acc += fl_elem(x.x, t0, w4.x);
            acc += fl_elem(x.y, t1, w4.y);
            acc += fl_elem(x.z, t2, w4.z);
            acc += fl_elem(x.w, t3, w4.w);

            CPA_WAIT0();            // next buffer landed (overlapped with compute)
            __syncthreads();        // all reads of 'cur' done; 'nxt' visible to all
            cur = nxt;
        }
    } else {
        // Generic fallback (not taken for the registered shape).
        long long N = (long long)B * A;
        const int stride = gridDim.x * blockDim.x;
        for (long long e = (long long)blockIdx.x * blockDim.x + tid; e < N; e += stride) {
            int bb = (int)(e / A);
            int a  = (int)(e - (long long)bb * A);
            float x = in[e];
            int t = __ldg(tg + (long long)a * B + bb);
            float w = __ldg(aw + a) * (LN2_F / (float)A);
            acc += fl_elem(x, t, w);
        }
    }

    // ---- block reduction + one atomic ----
    #pragma unroll
    for (int o = 16; o > 0; o >>= 1)
        acc += __shfl_down_sync(0xFFFFFFFFu, acc, o);

    __shared__ float wsum[NT / 32];
    int lane = tid & 31;
    int wid  = tid >> 5;
    if (lane == 0) wsum[wid] = acc;
    __syncthreads();

    if (wid == 0) {
        float v = (lane < NT / 32) ? wsum[lane] : 0.0f;
        #pragma unroll
        for (int o = 16; o > 0; o >>= 1)
            v += __shfl_down_sync(0xFFFFFFFFu, v, o);
        if (lane == 0)
            atomicAdd(out, v);
    }
}

extern "C" void kernel_launch(void* const* d_in, const int* in_sizes, int n_in,
                              void* d_out, int out_size) {
    const float* inputs  = (const float*)d_in[0];   // [B, A] f32
    const int*   targets = (const int*)d_in[1];     // [A, B] i32
    const float* aw      = (const float*)d_in[2];   // [A] f32
    float* out = (float*)d_out;

    int A = in_sizes[2];
    int B = in_sizes[0] / A;

    fl_init_out<<<1, 32>>>(out);
    focal_loss_kernel<<<GRID, NT>>>(inputs, targets, aw, out, B, A);
}

// round 13
// speedup vs baseline: 1.0364x; 1.0364x over previous
#include <cuda_runtime.h>
#include <cuda_bf16.h>

// FocalLoss: inputs [B, A] f32 probs, targets [A, B] i32 {0,1}, attr_loss_weight [A] f32.
// loss = sum_b mean_a( aw[a] * (1-x)^2 * bce(x, t) ),  bce = -log(t ? clamp(x) : 1-clamp(x))
// B = 1e6, A = 40.  ~324 MB streaming reduction.
//
// R13: fully latency-decoupled pipeline.
//  - inputs register-double-buffered (consumed one iteration after load)
//  - targets staged by cp.async into a 4-buffer ring
//  - 2 chunks per iteration -> 1 __syncthreads + 1 wait_group per 2 chunks
//  - XOR-mod7 smem swizzle keeps target LDS <=2-way conflict

#define A_NUM    40
#define NB       64                 // samples per chunk; 1e6/64 = 15625 chunks
#define NT       640                // threads; NB*A/4 = 640 items = 1/thread
#define GRID     296                // 148 SMs * 2 CTAs
#define ROWB     272                // bytes per attr row in smem
#define BUFB     (A_NUM * ROWB)     // 10880 B per buffer
#define NBUF     4

#define LN2_F 0.6931471805599453f

__global__ void fl_init_out(float* out) {
    if (threadIdx.x == 0) out[0] = 0.0f;
}

__device__ __forceinline__ void cpa16(unsigned s, const void* g) {
    asm volatile("cp.async.cg.shared.global [%0], [%1], 16;\n" :: "r"(s), "l"(g));
}
#define CPA_COMMIT() asm volatile("cp.async.commit_group;\n" ::: "memory")
#define CPA_WAIT0()  asm volatile("cp.async.wait_group 0;\n" ::: "memory")

__device__ __forceinline__ float fl_elem(float x, int t, float w) {
    // p = max(x,1e-12); upper clip (1-1e-12) rounds to 1.0f in f32 -> no-op.
    // (1-x)^2 == (1-p)^2 exactly (for x < 1e-12 both round to 1.0f).
    float p   = fmaxf(x, 1e-12f);
    float omp = 1.0f - p;
    float q   = t ? p : omp;
    return -w * (omp * omp) * __log2f(q);   // w includes aw*ln2/A
}

__global__ __launch_bounds__(NT, 2) void focal_loss_kernel(
    const float* __restrict__ in,     // [B, A]
    const int*   __restrict__ tg,     // [A, B]
    const float* __restrict__ aw,     // [A]
    float*       __restrict__ out,    // scalar
    int B, int A)
{
    float acc = 0.0f;
    const int tid = threadIdx.x;

    if (A == A_NUM && (B % NB) == 0 && blockDim.x == NT) {
        __shared__ __align__(16) float awv[A_NUM];
        __shared__ __align__(16) char  ts[NBUF * BUFB];   // 43520 B target ring

        if (tid < A_NUM) awv[tid] = aw[tid] * (LN2_F / (float)A_NUM);

        const float4* __restrict__ in4 = reinterpret_cast<const float4*>(in);
        const int nchunks = B / NB;                // 15625
        const int G = GRID;

        // ---- compute-side constants (1 item per thread) ----
        const int b  = tid / 10;                   // sample within chunk, 0..63
        const int a4 = 4 * (tid - 10 * b);         // first attr, {0,4,...,36}
        int roff[4];
        #pragma unroll
        for (int j = 0; j < 4; j++) {
            int a = a4 + j;
            roff[j] = a * ROWB + 16 * ((b >> 2) ^ (a % 7)) + 4 * (b & 3);
        }

        // ---- staging-side constants ----
        const int ta = tid >> 4;                   // attr row, 0..39
        const int tr = tid & 15;                   // 16B chunk, 0..15
        const int* gsrc = tg + (size_t)ta * B + 4 * tr;
        const unsigned sbase = (unsigned)__cvta_generic_to_shared(ts);
        const unsigned woff  = ta * ROWB + 16 * (tr ^ (ta % 7));

        const int c0 = blockIdx.x;

        // ---- prologue: stage chunks c0, c0+G into buffers 0,1; prefetch x0 ----
        cpa16(sbase + woff, gsrc + c0 * NB);
        CPA_COMMIT();
        if (c0 + G < nchunks)
            cpa16(sbase + BUFB + woff, gsrc + (c0 + G) * NB);
        CPA_COMMIT();

        float4 x0 = __ldcs(&in4[c0 * NT + tid]);

        CPA_WAIT0();
        __syncthreads();                           // targets + awv visible

        const float4 w4 = *reinterpret_cast<const float4*>(awv + a4);

        int bufA = 0;                              // pair base: 0 or 2
        for (int c = c0; c < nchunks; c += 2 * G) {
            const bool h1 = (c + G)     < nchunks; // second chunk this iter
            const bool p0 = (c + 2 * G) < nchunks; // next-iter chunk 0
            const bool p1 = (c + 3 * G) < nchunks; // next-iter chunk 1
            const int  nxt = bufA ^ 2;

            // stage next pair of target chunks (fly during both computes)
            if (p0) cpa16(sbase + nxt * BUFB + woff, gsrc + (c + 2 * G) * NB);
            CPA_COMMIT();
            if (p1) cpa16(sbase + (nxt + 1) * BUFB + woff, gsrc + (c + 3 * G) * NB);
            CPA_COMMIT();

            // prefetch second chunk's input (flies during compute of chunk c)
            float4 x1;
            if (h1) x1 = __ldcs(&in4[(c + G) * NT + tid]);

            // ---- compute chunk c (x0 resident since last iteration) ----
            {
                const char* tb = ts + bufA * BUFB;
                int t0 = *reinterpret_cast<const int*>(tb + roff[0]);
                int t1 = *reinterpret_cast<const int*>(tb + roff[1]);
                int t2 = *reinterpret_cast<const int*>(tb + roff[2]);
                int t3 = *reinterpret_cast<const int*>(tb + roff[3]);
                acc += fl_elem(x0.x, t0, w4.x);
                acc += fl_elem(x0.y, t1, w4.y);
                acc += fl_elem(x0.z, t2, w4.z);
                acc += fl_elem(x0.w, t3, w4.w);
            }

            // prefetch next iteration's first input (flies during compute of c+G)
            if (p0) x0 = __ldcs(&in4[(c + 2 * G) * NT + tid]);

            // ---- compute chunk c+G ----
            if (h1) {
                const char* tb = ts + (bufA + 1) * BUFB;
                int t0 = *reinterpret_cast<const int*>(tb + roff[0]);
                int t1 = *reinterpret_cast<const int*>(tb + roff[1]);
                int t2 = *reinterpret_cast<const int*>(tb + roff[2]);
                int t3 = *reinterpret_cast<const int*>(tb + roff[3]);
                acc += fl_elem(x1.x, t0, w4.x);
                acc += fl_elem(x1.y, t1, w4.y);
                acc += fl_elem(x1.z, t2, w4.z);
                acc += fl_elem(x1.w, t3, w4.w);
            }

            CPA_WAIT0();            // next pair landed (had 2 compute phases to fly)
            __syncthreads();        // readers of bufA pair done; nxt pair visible
            bufA = nxt;
        }
    } else {
        // Generic fallback (not taken for the registered shape).
        long long N = (long long)B * A;
        const int stride = gridDim.x * blockDim.x;
        for (long long e = (long long)blockIdx.x * blockDim.x + tid; e < N; e += stride) {
            int bb = (int)(e / A);
            int a  = (int)(e - (long long)bb * A);
            float x = in[e];
            int t = __ldg(tg + (long long)a * B + bb);
            float w = __ldg(aw + a) * (LN2_F / (float)A);
            acc += fl_elem(x, t, w);
        }
    }

    // ---- block reduction + one atomic ----
    #pragma unroll
    for (int o = 16; o > 0; o >>= 1)
        acc += __shfl_down_sync(0xFFFFFFFFu, acc, o);

    __shared__ float wsum[NT / 32];
    int lane = tid & 31;
    int wid  = tid >> 5;
    if (lane == 0) wsum[wid] = acc;
    __syncthreads();

    if (wid == 0) {
        float v = (lane < NT / 32) ? wsum[lane] : 0.0f;
        #pragma unroll
        for (int o = 16; o > 0; o >>= 1)
            v += __shfl_down_sync(0xFFFFFFFFu, v, o);
        if (lane == 0)
            atomicAdd(out, v);
    }
}

extern "C" void kernel_launch(void* const* d_in, const int* in_sizes, int n_in,
                              void* d_out, int out_size) {
    const float* inputs  = (const float*)d_in[0];   // [B, A] f32
    const int*   targets = (const int*)d_in[1];     // [A, B] i32
    const float* aw      = (const float*)d_in[2];   // [A] f32
    float* out = (float*)d_out;

    int A = in_sizes[2];
    int B = in_sizes[0] / A;

    fl_init_out<<<1, 32>>>(out);
    focal_loss_kernel<<<GRID, NT>>>(inputs, targets, aw, out, B, A);
}